// round 15
// baseline (speedup 1.0000x reference)
#include <cuda_runtime.h>
#include <cuda_fp16.h>
#include <cstdint>
#include <math.h>

// Problem constants
static constexpr int B_  = 2;
static constexpr int S_  = 2048;
static constexpr int D_  = 512;
static constexpr int H_  = 8;
static constexpr int DK_ = 64;
static constexpr int DF_ = 2048;
static constexpr int M_  = B_ * S_;
static constexpr long long QKV_ELEMS = (long long)B_ * H_ * S_ * DK_;

// -------- scratch (device globals; no allocation allowed) --------
__device__ __half g_xh [(long long)M_ * D_];
__device__ __half g_q  [QKV_ELEMS];
__device__ __half g_k  [QKV_ELEMS];
__device__ __half g_v  [QKV_ELEMS];
__device__ __half g_och[(long long)M_ * D_];
__device__ __half g_h1h[(long long)M_ * D_];
__device__ __half g_hh [(long long)M_ * D_];
__device__ __half g_ff [(long long)M_ * DF_];
__device__ __half g_h2h[(long long)M_ * D_];
__device__ __half g_Wqh[(long long)H_ * D_ * DK_];   // [h][512][64]  (natural [K,N])
__device__ __half g_Wkh[(long long)H_ * D_ * DK_];
__device__ __half g_Wvh[(long long)H_ * D_ * DK_];
__device__ __half g_Woh[(long long)D_ * D_];         // [512][512]
__device__ __half g_W1h[(long long)D_ * DF_];        // [512][2048]
__device__ __half g_W2h[(long long)DF_ * D_];        // [2048][512]

// -------- batched offset descriptor --------
struct Off { int div; long long s1; long long s2; };
__device__ __forceinline__ long long offz(Off o, int z) {
    return (long long)(z / o.div) * o.s1 + (long long)(z % o.div) * o.s2;
}

// -------- conversion segment descriptors --------
struct CvtSeg { const float* src; __half* dst; int nblk; };
struct CvtArgs4 { CvtSeg s[4]; };
struct CvtArgs3 { CvtSeg s[3]; };

// ===================== PTX helpers =====================
__device__ __forceinline__ uint32_t smem_u32(const void* p) {
    uint32_t a;
    asm("{ .reg .u64 t; cvta.to.shared.u64 t, %1; cvt.u32.u64 %0, t; }" : "=r"(a) : "l"(p));
    return a;
}
__device__ __forceinline__ void cp16(uint32_t dst, const void* src) {
    asm volatile("cp.async.cg.shared.global [%0], [%1], 16;"
                 :: "r"(dst), "l"(__cvta_generic_to_global(src)) : "memory");
}
__device__ __forceinline__ void mma16(float* d, const uint32_t* a, const uint32_t* b) {
    asm volatile(
        "mma.sync.aligned.m16n8k16.row.col.f32.f16.f16.f32 "
        "{%0,%1,%2,%3}, {%4,%5,%6,%7}, {%8,%9}, {%0,%1,%2,%3};"
        : "+f"(d[0]), "+f"(d[1]), "+f"(d[2]), "+f"(d[3])
        : "r"(a[0]), "r"(a[1]), "r"(a[2]), "r"(a[3]), "r"(b[0]), "r"(b[1]));
}
__device__ __forceinline__ void ldsm4(uint32_t* r, uint32_t a) {
    asm volatile("ldmatrix.sync.aligned.m8n8.x4.shared.b16 {%0,%1,%2,%3}, [%4];"
                 : "=r"(r[0]), "=r"(r[1]), "=r"(r[2]), "=r"(r[3]) : "r"(a));
}
__device__ __forceinline__ void ldsm4t(uint32_t* r, uint32_t a) {
    asm volatile("ldmatrix.sync.aligned.m8n8.x4.trans.shared.b16 {%0,%1,%2,%3}, [%4];"
                 : "=r"(r[0]), "=r"(r[1]), "=r"(r[2]), "=r"(r[3]) : "r"(a));
}
__device__ __forceinline__ uint32_t ldh2(const __half* p) {
    return *reinterpret_cast<const uint32_t*>(p);
}
__device__ __forceinline__ uint32_t h2scale(uint32_t x, __half2 s) {
    __half2 v = __hmul2(*reinterpret_cast<__half2*>(&x), s);
    return *reinterpret_cast<uint32_t*>(&v);
}
__device__ __forceinline__ uint32_t packh2(float a, float b) {
    __half2 h = __floats2half2_rn(a, b);
    return *reinterpret_cast<uint32_t*>(&h);
}
// one block converts 1024 fp32 -> half (256 threads x 4 elems)
__device__ __forceinline__ void cvt_block(const float* src, __half* dst, int blk) {
    const float4* s4 = reinterpret_cast<const float4*>(src);
    uint2* d2 = reinterpret_cast<uint2*>(dst);
    int e = blk * 256 + threadIdx.x;
    float4 v = s4[e];
    __half2 lo = __floats2half2_rn(v.x, v.y);
    __half2 hi = __floats2half2_rn(v.z, v.w);
    uint2 o;
    o.x = *reinterpret_cast<uint32_t*>(&lo);
    o.y = *reinterpret_cast<uint32_t*>(&hi);
    d2[e] = o;
}

// =====================================================================
// fp16 mma GEMM, B in NATURAL [K,N] row-major layout (trans ldmatrix).
//   C = A @ B (+bias)(+relu|+residual)   — ALL I/O half (accum fp32)
// A half row-major [M,K]. BM = 32*MI, BK=64, BN in {64,128}.
// 3-stage cp.async pipeline, one barrier per mainloop iteration.
// EPI: 0 bias; 1 bias+relu; 2 bias+half-residual. Output always half.
// MULTI: blockIdx.x selects (B, bias, Ch) triple, bn = 0.
// =====================================================================
template<int MI, int BN, int EPI, bool MULTI>
__global__ void __launch_bounds__(2 * (BN / 32) * 32, (MI == 2) ? 4 : 2)
gemm_h(const __half* __restrict__ A,
       const __half* __restrict__ B0, const __half* __restrict__ B1, const __half* __restrict__ B2,
       const float* __restrict__ g0, const float* __restrict__ g1, const float* __restrict__ g2,
       const __half* __restrict__ res,
       __half* __restrict__ Ch0, __half* __restrict__ Ch1, __half* __restrict__ Ch2,
       int M, int N, int K, int ldc,
       Off oA, Off oB, Off oBias, Off oC)
{
    constexpr int BM = 32 * MI;
    constexpr int BK = 64;
    constexpr int STG = 3;                        // pipeline stages
    constexpr int SW = 72;                        // A smem row stride (halves)
    constexpr int BWp = BN + 8;                   // B smem row stride (halves)
    constexpr int NWN = BN / 32;
    constexpr int NT  = 2 * NWN * 32;             // 128 or 256 threads
    constexpr int A_H = BM * SW;
    constexpr int B_H = BK * BWp;
    constexpr int A_ITERS = (BM * (BK / 8)) / NT;
    constexpr int B_ITERS = (BK * (BN / 8)) / NT;
    constexpr int BCH = BN / 8;                   // 16B chunks per B row

    extern __shared__ __half smh[];
    __half* sA = smh;                 // [STG][BM][SW]
    __half* sB = smh + STG * A_H;     // [STG][BK][BWp]
    const uint32_t uA = smem_u32(sA);
    const uint32_t uB = smem_u32(sB);

    const int tid  = threadIdx.x;
    const int wid  = tid >> 5;
    const int lane = tid & 31;
    const int gid  = lane >> 2;
    const int tig  = lane & 3;
    const int wn   = wid % NWN;
    const int wm   = wid / NWN;
    const int z    = blockIdx.z;
    const int sel  = MULTI ? blockIdx.x : 0;

    const __half* Bsel = (sel == 0) ? B0 : (sel == 1 ? B1 : B2);
    const float*  gsel = (sel == 0) ? g0 : (sel == 1 ? g1 : g2);
    __half*       Chsel = (sel == 0) ? Ch0 : (sel == 1 ? Ch1 : Ch2);

    const __half* Am = A + offz(oA, z);
    Bsel += offz(oB, z);
    const long long cOff = offz(oC, z);
    const float* bptr = (gsel != nullptr) ? gsel + offz(oBias, z) : nullptr;

    const long long bm = (long long)blockIdx.y * BM;
    const long long bn = MULTI ? 0 : (long long)blockIdx.x * BN;
    const int T = K / BK;

    const __half* aBase = Am + bm * K;
    const __half* bBase = Bsel + bn;              // [K,N]: row stride N

    auto stage = [&](int t) {
        const int buf = t % STG;
        const __half* aSrc = aBase + (long long)t * BK;
        const __half* bSrc = bBase + (long long)t * BK * N;
        const uint32_t aDst = uA + (uint32_t)buf * A_H * 2;
        const uint32_t bDst = uB + (uint32_t)buf * B_H * 2;
#pragma unroll
        for (int i = 0; i < A_ITERS; i++) {
            int e = tid + i * NT;
            int r = e >> 3, c = e & 7;            // 8 chunks of 8 halves per 64-half row
            cp16(aDst + (uint32_t)(r * SW + c * 8) * 2, aSrc + (long long)r * K + c * 8);
        }
#pragma unroll
        for (int i = 0; i < B_ITERS; i++) {
            int e = tid + i * NT;
            int r = e / BCH, c = e % BCH;
            cp16(bDst + (uint32_t)(r * BWp + c * 8) * 2, bSrc + (long long)r * N + c * 8);
        }
        asm volatile("cp.async.commit_group;" ::: "memory");
    };

    float acc[MI][4][4];
#pragma unroll
    for (int i = 0; i < MI; i++)
#pragma unroll
        for (int j = 0; j < 4; j++)
#pragma unroll
            for (int r = 0; r < 4; r++) acc[i][j][r] = 0.0f;

    // ldmatrix lane-address components
    const int aRow = (lane & 7) + ((lane >> 3) & 1) * 8;
    const int aColSel = (lane >> 4) * 8;
    const int bRowSel = (lane & 7) + ((lane >> 3) & 1) * 8;  // k within tile
    const int bColSel = (lane >> 4) * 8;                      // n sub-offset

    stage(0);
    if (T > 1) stage(1);
    for (int t = 0; t < T; t++) {
        if (t + 2 < T) {
            asm volatile("cp.async.wait_group 1;" ::: "memory");
        } else {
            asm volatile("cp.async.wait_group 0;" ::: "memory");
        }
        __syncthreads();                    // buffer t published; iter t-1 readers done
        if (t + 2 < T) stage(t + 2);        // overwrites buffer (t-1)%3 — safe

        const uint32_t uAs = uA + (uint32_t)(t % STG) * A_H * 2;
        const uint32_t uBs = uB + (uint32_t)(t % STG) * B_H * 2;
#pragma unroll
        for (int ks = 0; ks < BK / 16; ks++) {
            const int kc = ks * 16;
            uint32_t af[MI][4];
#pragma unroll
            for (int mi = 0; mi < MI; mi++)
                ldsm4(af[mi], uAs + (uint32_t)((wm * (MI * 16) + mi * 16 + aRow) * SW + kc + aColSel) * 2);
            uint32_t bf[4][2];
#pragma unroll
            for (int p = 0; p < 2; p++) {
                uint32_t tmp[4];
                ldsm4t(tmp, uBs + (uint32_t)((kc + bRowSel) * BWp + wn * 32 + p * 16 + bColSel) * 2);
                bf[2 * p][0] = tmp[0]; bf[2 * p][1] = tmp[1];
                bf[2 * p + 1][0] = tmp[2]; bf[2 * p + 1][1] = tmp[3];
            }
#pragma unroll
            for (int mi = 0; mi < MI; mi++)
#pragma unroll
                for (int nj = 0; nj < 4; nj++)
                    mma16(acc[mi][nj], af[mi], bf[nj]);
        }
    }

    // ---- epilogue (all-half I/O) ----
#pragma unroll
    for (int mi = 0; mi < MI; mi++) {
        const long long m0 = bm + wm * (MI * 16) + mi * 16 + gid;
#pragma unroll
        for (int nj = 0; nj < 4; nj++) {
            const long long n0 = bn + wn * 32 + nj * 8 + tig * 2;
            float2 bb = make_float2(0.0f, 0.0f);
            if (bptr) bb = *reinterpret_cast<const float2*>(bptr + n0);

            float2 o0, o1;
            o0.x = acc[mi][nj][0] + bb.x;
            o0.y = acc[mi][nj][1] + bb.y;
            o1.x = acc[mi][nj][2] + bb.x;
            o1.y = acc[mi][nj][3] + bb.y;
            if (EPI == 1) {
                o0.x = fmaxf(o0.x, 0.0f); o0.y = fmaxf(o0.y, 0.0f);
                o1.x = fmaxf(o1.x, 0.0f); o1.y = fmaxf(o1.y, 0.0f);
            }
            if (EPI == 2) {
                __half2 r0 = *reinterpret_cast<const __half2*>(res + m0 * ldc + n0);
                __half2 r1 = *reinterpret_cast<const __half2*>(res + (m0 + 8) * ldc + n0);
                o0.x += __low2float(r0); o0.y += __high2float(r0);
                o1.x += __low2float(r1); o1.y += __high2float(r1);
            }
            __half* c = Chsel + cOff;
            *reinterpret_cast<__half2*>(c + m0 * ldc + n0) = __floats2half2_rn(o0.x, o0.y);
            *reinterpret_cast<__half2*>(c + (m0 + 8) * ldc + n0) = __floats2half2_rn(o1.x, o1.y);
        }
    }
}

// =====================================================================
// Fused flash attention (fp16 mma + ldmatrix, fp32 softmax/accum) with
// PIGGYBACKED weight conversion: blocks with blockIdx.x >= QX convert
// fp32 weight segments (Wo/W1/W2) to half and exit — overlapping the
// conversion traffic with flash's latency-bound mma phase.
// =====================================================================
static constexpr int FLASH_QX = S_ / 128;    // 16 attention x-blocks

__global__ void __launch_bounds__(256, 2)
flash_h(const __half* __restrict__ Q, const __half* __restrict__ K,
        const __half* __restrict__ V, __half* __restrict__ Och, CvtArgs3 cvt)
{
    // ---- piggyback converter blocks ----
    if (blockIdx.x >= FLASH_QX) {
        int b = (blockIdx.x - FLASH_QX) * gridDim.y + blockIdx.y;
#pragma unroll
        for (int i = 0; i < 3; i++) {
            if (b < cvt.s[i].nblk) { cvt_block(cvt.s[i].src, cvt.s[i].dst, b); return; }
            b -= cvt.s[i].nblk;
        }
        return;
    }

    constexpr int PW = 72;                     // padded row stride (halves)
    constexpr int STG = 3;
    constexpr int QP_H = 128 * PW;
    constexpr int KV_H = 64 * PW;
    constexpr int T = S_ / 64;                 // 32 key tiles

    extern __shared__ __half smh[];
    __half* sQP = smh;                         // Q staging only
    __half* sK  = smh + QP_H;                  // [STG][64 keys][PW]
    __half* sV  = sK + STG * KV_H;             // [STG][64 keys][PW]
    const uint32_t uK  = smem_u32(sK);
    const uint32_t uV  = smem_u32(sV);

    const int tid  = threadIdx.x;
    const int wid  = tid >> 5;
    const int lane = tid & 31;
    const int gid  = lane >> 2;
    const int tig  = lane & 3;
    const int wr   = wid * 16;

    const int z  = blockIdx.y;
    const int zb = z / H_;
    const int zh = z % H_;
    const long long m0 = (long long)blockIdx.x * 128;

    const __half* Qz = Q + (long long)z * S_ * DK_;
    const __half* Kz = K + (long long)z * S_ * DK_;
    const __half* Vz = V + (long long)z * S_ * DK_;

    // ---- stage Q tile [128][64] ----
#pragma unroll
    for (int i = 0; i < 4; i++) {
        int e = tid + i * 256;
        int r = e >> 3, c = e & 7;
        *reinterpret_cast<uint4*>(&sQP[r * PW + c * 8]) =
            *reinterpret_cast<const uint4*>(Qz + (m0 + r) * DK_ + c * 8);
    }
    __syncthreads();

    // ---- Q fragments, scaled by exact 0.125 ----
    const __half2 sc8 = __float2half2_rn(0.125f);
    uint32_t qf[4][4];
#pragma unroll
    for (int ks = 0; ks < 4; ks++) {
        const __half* qp = sQP + (wr + gid) * PW + ks * 16 + 2 * tig;
        qf[ks][0] = h2scale(ldh2(qp), sc8);
        qf[ks][1] = h2scale(ldh2(qp + 8 * PW), sc8);
        qf[ks][2] = h2scale(ldh2(qp + 8), sc8);
        qf[ks][3] = h2scale(ldh2(qp + 8 * PW + 8), sc8);
    }

    float oacc[8][4];
#pragma unroll
    for (int nj = 0; nj < 8; nj++)
#pragma unroll
        for (int r = 0; r < 4; r++) oacc[nj][r] = 0.0f;
    float mrow0 = -1e30f, mrow1 = -1e30f;
    float lrow0 = 0.0f,  lrow1 = 0.0f;

    auto stage = [&](int t) {
        const int buf = t % STG;
        const uint32_t kDst = uK + (uint32_t)buf * KV_H * 2;
        const uint32_t vDst = uV + (uint32_t)buf * KV_H * 2;
#pragma unroll
        for (int i = 0; i < 2; i++) {
            int e = tid + i * 256;
            int r = e >> 3, c = e & 7;
            cp16(kDst + (uint32_t)(r * PW + c * 8) * 2,
                 Kz + (long long)(t * 64 + r) * DK_ + c * 8);
        }
#pragma unroll
        for (int i = 0; i < 2; i++) {
            int e = tid + i * 256;
            int r = e >> 3, c = e & 7;
            cp16(vDst + (uint32_t)(r * PW + c * 8) * 2,
                 Vz + (long long)(t * 64 + r) * DK_ + c * 8);
        }
        asm volatile("cp.async.commit_group;" ::: "memory");
    };

    // ldmatrix lane-address components
    const int nRowSel = (lane >> 4) * 8 + (lane & 7);       // non-trans: row within 16
    const int nColSel = ((lane >> 3) & 1) * 8;              // non-trans: k sub-offset
    const int tRowSel = (lane & 7) + ((lane >> 3) & 1) * 8; // trans: k row within 16
    const int tColSel = (lane >> 4) * 8;                    // trans: n sub-offset

    stage(0);
    stage(1);
    for (int t = 0; t < T; t++) {
        if (t + 2 < T) {
            asm volatile("cp.async.wait_group 1;" ::: "memory");
        } else {
            asm volatile("cp.async.wait_group 0;" ::: "memory");
        }
        __syncthreads();                    // tile t published; iter t-1 readers done
        if (t + 2 < T) stage(t + 2);        // overwrites buffer (t-1)%3 — safe

        const uint32_t uKs = uK + (uint32_t)(t % STG) * KV_H * 2;
        const uint32_t uVs = uV + (uint32_t)(t % STG) * KV_H * 2;

        // ---- S = (Q/8) @ K^T : 16 x 64 per warp ----
        float sacc[8][4];
#pragma unroll
        for (int nj = 0; nj < 8; nj++)
#pragma unroll
            for (int r = 0; r < 4; r++) sacc[nj][r] = 0.0f;
#pragma unroll
        for (int ks = 0; ks < 4; ks++) {
            const int kc = ks * 16;
#pragma unroll
            for (int p = 0; p < 4; p++) {
                uint32_t tmp[4];
                ldsm4(tmp, uKs + (uint32_t)((p * 16 + nRowSel) * PW + kc + nColSel) * 2);
                mma16(sacc[2 * p], qf[ks], tmp);
                mma16(sacc[2 * p + 1], qf[ks], tmp + 2);
            }
        }

        // ---- online softmax (P packed to registers) ----
        float mx0 = -1e30f, mx1 = -1e30f;
#pragma unroll
        for (int nj = 0; nj < 8; nj++) {
            mx0 = fmaxf(mx0, fmaxf(sacc[nj][0], sacc[nj][1]));
            mx1 = fmaxf(mx1, fmaxf(sacc[nj][2], sacc[nj][3]));
        }
        mx0 = fmaxf(mx0, __shfl_xor_sync(0xffffffffu, mx0, 1));
        mx0 = fmaxf(mx0, __shfl_xor_sync(0xffffffffu, mx0, 2));
        mx1 = fmaxf(mx1, __shfl_xor_sync(0xffffffffu, mx1, 1));
        mx1 = fmaxf(mx1, __shfl_xor_sync(0xffffffffu, mx1, 2));

        const float mn0 = fmaxf(mrow0, mx0);
        const float mn1 = fmaxf(mrow1, mx1);
        const float sc0 = __expf(mrow0 - mn0);
        const float sc1 = __expf(mrow1 - mn1);
        mrow0 = mn0; mrow1 = mn1;

        uint32_t puint[16];
        float ls0 = 0.0f, ls1 = 0.0f;
#pragma unroll
        for (int nj = 0; nj < 8; nj++) {
            float e0 = __expf(sacc[nj][0] - mn0);
            float e1 = __expf(sacc[nj][1] - mn0);
            float e2 = __expf(sacc[nj][2] - mn1);
            float e3 = __expf(sacc[nj][3] - mn1);
            ls0 += e0 + e1;
            ls1 += e2 + e3;
            puint[2 * nj]     = packh2(e0, e1);
            puint[2 * nj + 1] = packh2(e2, e3);
        }
        ls0 += __shfl_xor_sync(0xffffffffu, ls0, 1);
        ls0 += __shfl_xor_sync(0xffffffffu, ls0, 2);
        ls1 += __shfl_xor_sync(0xffffffffu, ls1, 1);
        ls1 += __shfl_xor_sync(0xffffffffu, ls1, 2);
        lrow0 = lrow0 * sc0 + ls0;
        lrow1 = lrow1 * sc1 + ls1;

#pragma unroll
        for (int nj = 0; nj < 8; nj++) {
            oacc[nj][0] *= sc0; oacc[nj][1] *= sc0;
            oacc[nj][2] *= sc1; oacc[nj][3] *= sc1;
        }

        // ---- O += P @ V  (P from registers; V [keys][dk] via trans) ----
#pragma unroll
        for (int ks = 0; ks < 4; ks++) {
            const int kc = ks * 16;
            uint32_t pf[4] = {puint[4 * ks], puint[4 * ks + 1],
                              puint[4 * ks + 2], puint[4 * ks + 3]};
#pragma unroll
            for (int p = 0; p < 4; p++) {
                uint32_t tmp[4];
                ldsm4t(tmp, uVs + (uint32_t)((kc + tRowSel) * PW + p * 16 + tColSel) * 2);
                mma16(oacc[2 * p], pf, tmp);
                mma16(oacc[2 * p + 1], pf, tmp + 2);
            }
        }
    }

    // ---- epilogue: normalize, write half into concat layout ----
    const float inv0 = 1.0f / lrow0;
    const float inv1 = 1.0f / lrow1;
    const long long row0 = (long long)zb * S_ + m0 + wr + gid;
    const long long row1 = row0 + 8;
    __half* o0 = Och + row0 * D_ + zh * DK_;
    __half* o1 = Och + row1 * D_ + zh * DK_;
#pragma unroll
    for (int nj = 0; nj < 8; nj++) {
        const int c = nj * 8 + tig * 2;
        *reinterpret_cast<__half2*>(o0 + c) =
            __floats2half2_rn(oacc[nj][0] * inv0, oacc[nj][1] * inv0);
        *reinterpret_cast<__half2*>(o1 + c) =
            __floats2half2_rn(oacc[nj][2] * inv1, oacc[nj][3] * inv1);
    }
}

// =====================================================================
// Segmented fp32 -> fp16 conversion (x + QKV weights only).
// =====================================================================
__global__ void __launch_bounds__(256)
f2h_qkv(CvtArgs4 a)
{
    int b = blockIdx.x;
#pragma unroll
    for (int i = 0; i < 4; i++) {
        if (b < a.s[i].nblk) { cvt_block(a.s[i].src, a.s[i].dst, b); return; }
        b -= a.s[i].nblk;
    }
}

// =====================================================================
// Row LayerNorm, HALF input. Writes fp32 out and/or half outh (either
// may be null). Stats computed in fp32.
// =====================================================================
__global__ void __launch_bounds__(128)
layernorm_h(const __half* __restrict__ in, const float* __restrict__ g,
            const float* __restrict__ b, float* __restrict__ outf,
            __half* __restrict__ outh)
{
    const int tid = threadIdx.x;
    const uint2 hv = reinterpret_cast<const uint2*>(in + (long long)blockIdx.x * D_)[tid];
    __half2 h01 = *reinterpret_cast<const __half2*>(&hv.x);
    __half2 h23 = *reinterpret_cast<const __half2*>(&hv.y);
    float4 v;
    v.x = __low2float(h01); v.y = __high2float(h01);
    v.z = __low2float(h23); v.w = __high2float(h23);

    float s  = v.x + v.y + v.z + v.w;
    float sq = v.x * v.x + v.y * v.y + v.z * v.z + v.w * v.w;
#pragma unroll
    for (int o = 16; o; o >>= 1) {
        s  += __shfl_xor_sync(0xffffffffu, s, o);
        sq += __shfl_xor_sync(0xffffffffu, sq, o);
    }
    __shared__ float ssum[4], ssq[4];
    if ((tid & 31) == 0) { ssum[tid >> 5] = s; ssq[tid >> 5] = sq; }
    __syncthreads();
    s  = ssum[0] + ssum[1] + ssum[2] + ssum[3];
    sq = ssq[0] + ssq[1] + ssq[2] + ssq[3];

    const float mu  = s * (1.0f / D_);
    float var = sq * (1.0f / D_) - mu * mu;
    var = fmaxf(var, 0.0f);
    const float rstd = rsqrtf(var + 1e-5f);

    float4 gg = reinterpret_cast<const float4*>(g)[tid];
    float4 bb = reinterpret_cast<const float4*>(b)[tid];
    float4 o4;
    o4.x = (v.x - mu) * rstd * gg.x + bb.x;
    o4.y = (v.y - mu) * rstd * gg.y + bb.y;
    o4.z = (v.z - mu) * rstd * gg.z + bb.z;
    o4.w = (v.w - mu) * rstd * gg.w + bb.w;
    if (outf != nullptr)
        reinterpret_cast<float4*>(outf + (long long)blockIdx.x * D_)[tid] = o4;
    if (outh != nullptr) {
        __half2 lo = __floats2half2_rn(o4.x, o4.y);
        __half2 hi = __floats2half2_rn(o4.z, o4.w);
        uint2 o;
        o.x = *reinterpret_cast<uint32_t*>(&lo);
        o.y = *reinterpret_cast<uint32_t*>(&hi);
        reinterpret_cast<uint2*>(outh + (long long)blockIdx.x * D_)[tid] = o;
    }
}

// =====================================================================
// Launcher
// =====================================================================
static constexpr int SMEM_M4N64  = 3 * (128 * 72 + 64 * 72) * 2;     // 82944
static constexpr int SMEM_M2N64  = 3 * (64 * 72 + 64 * 72) * 2;      // 55296
static constexpr int SMEM_M4N128 = 3 * (128 * 72 + 64 * 136) * 2;    // 107520
static constexpr int SMEM_FLASH  = (128 * 72 + 6 * 64 * 72) * 2;     // 73728

extern "C" void kernel_launch(void* const* d_in, const int* in_sizes, int n_in,
                              void* d_out, int out_size)
{
    (void)in_sizes; (void)n_in; (void)out_size;
    const float* x     = (const float*)d_in[0];
    const float* Wq    = (const float*)d_in[1];
    const float* bq    = (const float*)d_in[2];
    const float* Wk    = (const float*)d_in[3];
    const float* bk    = (const float*)d_in[4];
    const float* Wv    = (const float*)d_in[5];
    const float* bv    = (const float*)d_in[6];
    const float* Wo    = (const float*)d_in[7];
    const float* bo    = (const float*)d_in[8];
    const float* ln1_g = (const float*)d_in[9];
    const float* ln1_b = (const float*)d_in[10];
    const float* W1    = (const float*)d_in[11];
    const float* b1    = (const float*)d_in[12];
    const float* W2    = (const float*)d_in[13];
    const float* b2    = (const float*)d_in[14];
    const float* ln2_g = (const float*)d_in[15];
    const float* ln2_b = (const float*)d_in[16];
    float* out = (float*)d_out;

    __half *xh, *q, *k, *v, *och, *h1h, *hh, *ff, *h2h;
    __half *Wqh, *Wkh, *Wvh, *Woh, *W1h, *W2h;
    cudaGetSymbolAddress((void**)&xh,  g_xh);
    cudaGetSymbolAddress((void**)&q,   g_q);
    cudaGetSymbolAddress((void**)&k,   g_k);
    cudaGetSymbolAddress((void**)&v,   g_v);
    cudaGetSymbolAddress((void**)&och, g_och);
    cudaGetSymbolAddress((void**)&h1h, g_h1h);
    cudaGetSymbolAddress((void**)&hh,  g_hh);
    cudaGetSymbolAddress((void**)&ff,  g_ff);
    cudaGetSymbolAddress((void**)&h2h, g_h2h);
    cudaGetSymbolAddress((void**)&Wqh, g_Wqh);
    cudaGetSymbolAddress((void**)&Wkh, g_Wkh);
    cudaGetSymbolAddress((void**)&Wvh, g_Wvh);
    cudaGetSymbolAddress((void**)&Woh, g_Woh);
    cudaGetSymbolAddress((void**)&W1h, g_W1h);
    cudaGetSymbolAddress((void**)&W2h, g_W2h);

    cudaFuncSetAttribute(gemm_h<4, 64, 0, true>,   cudaFuncAttributeMaxDynamicSharedMemorySize, SMEM_M4N64);
    cudaFuncSetAttribute(gemm_h<2, 64, 2, false>,  cudaFuncAttributeMaxDynamicSharedMemorySize, SMEM_M2N64);
    cudaFuncSetAttribute(gemm_h<4, 128, 1, false>, cudaFuncAttributeMaxDynamicSharedMemorySize, SMEM_M4N128);
    cudaFuncSetAttribute(flash_h,                  cudaFuncAttributeMaxDynamicSharedMemorySize, SMEM_FLASH);

    const Off lin0      = {1, 0, 0};
    const Off oA_qkv    = {H_, (long long)S_ * D_, 0};
    const Off oB_qkv    = {H_, 0, (long long)D_ * DK_};
    const Off oBias_qkv = {H_, 0, (long long)DK_};
    const Off oC_qkv    = {1, (long long)S_ * DK_, 0};

    // ---- 0. convert QKV dependencies only (x, Wq, Wk, Wv) ----
    CvtArgs4 ca;
    ca.s[0] = {x,  xh,  (int)((long long)M_ * D_ / 1024)};        // 2048
    ca.s[1] = {Wq, Wqh, (int)((long long)H_ * D_ * DK_ / 1024)};  // 256
    ca.s[2] = {Wk, Wkh, (int)((long long)H_ * D_ * DK_ / 1024)};
    ca.s[3] = {Wv, Wvh, (int)((long long)H_ * D_ * DK_ / 1024)};
    int totBlk = 0;
    for (int i = 0; i < 4; i++) totBlk += ca.s[i].nblk;
    f2h_qkv<<<totBlk, 256>>>(ca);

    // ---- 1. merged QKV projections (BM=128, BK=64, T=8) ----
    gemm_h<4, 64, 0, true><<<dim3(3, 16, B_ * H_), 128, SMEM_M4N64>>>(
        xh, Wqh, Wkh, Wvh, bq, bk, bv, nullptr, q, k, v,
        S_, DK_, D_, DK_, oA_qkv, oB_qkv, oBias_qkv, oC_qkv);

    // ---- 2. flash attention + piggybacked Wo/W1/W2 conversion ----
    CvtArgs3 cw;
    cw.s[0] = {Wo, Woh, (int)((long long)D_ * D_ / 1024)};    // 256
    cw.s[1] = {W1, W1h, (int)((long long)D_ * DF_ / 1024)};   // 1024
    cw.s[2] = {W2, W2h, (int)((long long)DF_ * D_ / 1024)};   // 1024
    int cvtBlk = cw.s[0].nblk + cw.s[1].nblk + cw.s[2].nblk;  // 2304
    int extraX = (cvtBlk + (B_ * H_) - 1) / (B_ * H_);        // 144
    flash_h<<<dim3(FLASH_QX + extraX, B_ * H_), 256, SMEM_FLASH>>>(q, k, v, och, cw);

    // ---- 3. h1h = xh + och @ Wo + bo  (half residual, half out) ----
    gemm_h<2, 64, 2, false><<<dim3(8, 64, 1), 128, SMEM_M2N64>>>(
        och, Woh, Woh, Woh, bo, bo, bo, xh, h1h, h1h, h1h,
        M_, D_, D_, D_, lin0, lin0, lin0, lin0);

    // ---- 4. hh = LN1(h1h)  (half in, half out only) ----
    layernorm_h<<<M_, 128>>>(h1h, ln1_g, ln1_b, nullptr, hh);

    // ---- 5. ff = relu(hh @ W1 + b1)  (BM=128, BN=128) ----
    gemm_h<4, 128, 1, false><<<dim3(16, 32, 1), 256, SMEM_M4N128>>>(
        hh, W1h, W1h, W1h, b1, b1, b1, nullptr, ff, ff, ff,
        M_, DF_, D_, DF_, lin0, lin0, lin0, lin0);

    // ---- 6. h2h = hh + ff @ W2 + b2  (half residual, half out) ----
    gemm_h<2, 64, 2, false><<<dim3(8, 64, 1), 128, SMEM_M2N64>>>(
        ff, W2h, W2h, W2h, b2, b2, b2, hh, h2h, h2h, h2h,
        M_, D_, DF_, D_, lin0, lin0, lin0, lin0);

    // ---- 7. out = LN2(h2h)  (half in, fp32 out) ----
    layernorm_h<<<M_, 128>>>(h2h, ln2_g, ln2_b, out, nullptr);
}

// round 16
// speedup vs baseline: 1.1129x; 1.1129x over previous
#include <cuda_runtime.h>
#include <cuda_fp16.h>
#include <cstdint>
#include <math.h>

// Problem constants
static constexpr int B_  = 2;
static constexpr int S_  = 2048;
static constexpr int D_  = 512;
static constexpr int H_  = 8;
static constexpr int DK_ = 64;
static constexpr int DF_ = 2048;
static constexpr int M_  = B_ * S_;
static constexpr long long QKV_ELEMS = (long long)B_ * H_ * S_ * DK_;

// -------- scratch (device globals; no allocation allowed) --------
__device__ __half g_xh [(long long)M_ * D_];
__device__ __half g_q  [QKV_ELEMS];
__device__ __half g_k  [QKV_ELEMS];
__device__ __half g_v  [QKV_ELEMS];
__device__ __half g_och[(long long)M_ * D_];
__device__ __half g_h1h[(long long)M_ * D_];
__device__ __half g_hh [(long long)M_ * D_];
__device__ __half g_ff [(long long)M_ * DF_];
__device__ __half g_h2h[(long long)M_ * D_];
__device__ __half g_Wqh[(long long)H_ * D_ * DK_];   // [h][512][64]  (natural [K,N])
__device__ __half g_Wkh[(long long)H_ * D_ * DK_];
__device__ __half g_Wvh[(long long)H_ * D_ * DK_];
__device__ __half g_Woh[(long long)D_ * D_];         // [512][512]
__device__ __half g_W1h[(long long)D_ * DF_];        // [512][2048]
__device__ __half g_W2h[(long long)DF_ * D_];        // [2048][512]

// -------- batched offset descriptor --------
struct Off { int div; long long s1; long long s2; };
__device__ __forceinline__ long long offz(Off o, int z) {
    return (long long)(z / o.div) * o.s1 + (long long)(z % o.div) * o.s2;
}

// ===================== PTX helpers =====================
__device__ __forceinline__ uint32_t smem_u32(const void* p) {
    uint32_t a;
    asm("{ .reg .u64 t; cvta.to.shared.u64 t, %1; cvt.u32.u64 %0, t; }" : "=r"(a) : "l"(p));
    return a;
}
__device__ __forceinline__ void cp16(uint32_t dst, const void* src) {
    asm volatile("cp.async.cg.shared.global [%0], [%1], 16;"
                 :: "r"(dst), "l"(__cvta_generic_to_global(src)) : "memory");
}
__device__ __forceinline__ void mma16(float* d, const uint32_t* a, const uint32_t* b) {
    asm volatile(
        "mma.sync.aligned.m16n8k16.row.col.f32.f16.f16.f32 "
        "{%0,%1,%2,%3}, {%4,%5,%6,%7}, {%8,%9}, {%0,%1,%2,%3};"
        : "+f"(d[0]), "+f"(d[1]), "+f"(d[2]), "+f"(d[3])
        : "r"(a[0]), "r"(a[1]), "r"(a[2]), "r"(a[3]), "r"(b[0]), "r"(b[1]));
}
__device__ __forceinline__ void ldsm4(uint32_t* r, uint32_t a) {
    asm volatile("ldmatrix.sync.aligned.m8n8.x4.shared.b16 {%0,%1,%2,%3}, [%4];"
                 : "=r"(r[0]), "=r"(r[1]), "=r"(r[2]), "=r"(r[3]) : "r"(a));
}
__device__ __forceinline__ void ldsm4t(uint32_t* r, uint32_t a) {
    asm volatile("ldmatrix.sync.aligned.m8n8.x4.trans.shared.b16 {%0,%1,%2,%3}, [%4];"
                 : "=r"(r[0]), "=r"(r[1]), "=r"(r[2]), "=r"(r[3]) : "r"(a));
}
__device__ __forceinline__ uint32_t ldh2(const __half* p) {
    return *reinterpret_cast<const uint32_t*>(p);
}
__device__ __forceinline__ uint32_t h2scale(uint32_t x, __half2 s) {
    __half2 v = __hmul2(*reinterpret_cast<__half2*>(&x), s);
    return *reinterpret_cast<uint32_t*>(&v);
}
__device__ __forceinline__ uint32_t packh2(float a, float b) {
    __half2 h = __floats2half2_rn(a, b);
    return *reinterpret_cast<uint32_t*>(&h);
}

// =====================================================================
// fp16 mma GEMM, B in NATURAL [K,N] row-major layout (trans ldmatrix).
//   C = A @ B (+bias)(+relu|+residual)   — ALL I/O half (accum fp32)
// A half row-major [M,K]. BM = 32*MI, BK=64, BN in {64,128}.
// 3-stage cp.async pipeline, one barrier per mainloop iteration.
// EPI: 0 bias; 1 bias+relu; 2 bias+half-residual. Output always half.
// MULTI: blockIdx.x selects (B, bias, Ch) triple, bn = 0.
// =====================================================================
template<int MI, int BN, int EPI, bool MULTI>
__global__ void __launch_bounds__(2 * (BN / 32) * 32, (MI == 2) ? 4 : 2)
gemm_h(const __half* __restrict__ A,
       const __half* __restrict__ B0, const __half* __restrict__ B1, const __half* __restrict__ B2,
       const float* __restrict__ g0, const float* __restrict__ g1, const float* __restrict__ g2,
       const __half* __restrict__ res,
       __half* __restrict__ Ch0, __half* __restrict__ Ch1, __half* __restrict__ Ch2,
       int M, int N, int K, int ldc,
       Off oA, Off oB, Off oBias, Off oC)
{
    constexpr int BM = 32 * MI;
    constexpr int BK = 64;
    constexpr int STG = 3;                        // pipeline stages
    constexpr int SW = 72;                        // A smem row stride (halves)
    constexpr int BWp = BN + 8;                   // B smem row stride (halves)
    constexpr int NWN = BN / 32;
    constexpr int NT  = 2 * NWN * 32;             // 128 or 256 threads
    constexpr int A_H = BM * SW;
    constexpr int B_H = BK * BWp;
    constexpr int A_ITERS = (BM * (BK / 8)) / NT;
    constexpr int B_ITERS = (BK * (BN / 8)) / NT;
    constexpr int BCH = BN / 8;                   // 16B chunks per B row

    extern __shared__ __half smh[];
    __half* sA = smh;                 // [STG][BM][SW]
    __half* sB = smh + STG * A_H;     // [STG][BK][BWp]
    const uint32_t uA = smem_u32(sA);
    const uint32_t uB = smem_u32(sB);

    const int tid  = threadIdx.x;
    const int wid  = tid >> 5;
    const int lane = tid & 31;
    const int gid  = lane >> 2;
    const int tig  = lane & 3;
    const int wn   = wid % NWN;
    const int wm   = wid / NWN;
    const int z    = blockIdx.z;
    const int sel  = MULTI ? blockIdx.x : 0;

    const __half* Bsel = (sel == 0) ? B0 : (sel == 1 ? B1 : B2);
    const float*  gsel = (sel == 0) ? g0 : (sel == 1 ? g1 : g2);
    __half*       Chsel = (sel == 0) ? Ch0 : (sel == 1 ? Ch1 : Ch2);

    const __half* Am = A + offz(oA, z);
    Bsel += offz(oB, z);
    const long long cOff = offz(oC, z);
    const float* bptr = (gsel != nullptr) ? gsel + offz(oBias, z) : nullptr;

    const long long bm = (long long)blockIdx.y * BM;
    const long long bn = MULTI ? 0 : (long long)blockIdx.x * BN;
    const int T = K / BK;

    const __half* aBase = Am + bm * K;
    const __half* bBase = Bsel + bn;              // [K,N]: row stride N

    auto stage = [&](int t) {
        const int buf = t % STG;
        const __half* aSrc = aBase + (long long)t * BK;
        const __half* bSrc = bBase + (long long)t * BK * N;
        const uint32_t aDst = uA + (uint32_t)buf * A_H * 2;
        const uint32_t bDst = uB + (uint32_t)buf * B_H * 2;
#pragma unroll
        for (int i = 0; i < A_ITERS; i++) {
            int e = tid + i * NT;
            int r = e >> 3, c = e & 7;            // 8 chunks of 8 halves per 64-half row
            cp16(aDst + (uint32_t)(r * SW + c * 8) * 2, aSrc + (long long)r * K + c * 8);
        }
#pragma unroll
        for (int i = 0; i < B_ITERS; i++) {
            int e = tid + i * NT;
            int r = e / BCH, c = e % BCH;
            cp16(bDst + (uint32_t)(r * BWp + c * 8) * 2, bSrc + (long long)r * N + c * 8);
        }
        asm volatile("cp.async.commit_group;" ::: "memory");
    };

    float acc[MI][4][4];
#pragma unroll
    for (int i = 0; i < MI; i++)
#pragma unroll
        for (int j = 0; j < 4; j++)
#pragma unroll
            for (int r = 0; r < 4; r++) acc[i][j][r] = 0.0f;

    // ldmatrix lane-address components
    const int aRow = (lane & 7) + ((lane >> 3) & 1) * 8;
    const int aColSel = (lane >> 4) * 8;
    const int bRowSel = (lane & 7) + ((lane >> 3) & 1) * 8;  // k within tile
    const int bColSel = (lane >> 4) * 8;                      // n sub-offset

    stage(0);
    if (T > 1) stage(1);
    for (int t = 0; t < T; t++) {
        if (t + 2 < T) {
            asm volatile("cp.async.wait_group 1;" ::: "memory");
        } else {
            asm volatile("cp.async.wait_group 0;" ::: "memory");
        }
        __syncthreads();                    // buffer t published; iter t-1 readers done
        if (t + 2 < T) stage(t + 2);        // overwrites buffer (t-1)%3 — safe

        const uint32_t uAs = uA + (uint32_t)(t % STG) * A_H * 2;
        const uint32_t uBs = uB + (uint32_t)(t % STG) * B_H * 2;
#pragma unroll
        for (int ks = 0; ks < BK / 16; ks++) {
            const int kc = ks * 16;
            uint32_t af[MI][4];
#pragma unroll
            for (int mi = 0; mi < MI; mi++)
                ldsm4(af[mi], uAs + (uint32_t)((wm * (MI * 16) + mi * 16 + aRow) * SW + kc + aColSel) * 2);
            uint32_t bf[4][2];
#pragma unroll
            for (int p = 0; p < 2; p++) {
                uint32_t tmp[4];
                ldsm4t(tmp, uBs + (uint32_t)((kc + bRowSel) * BWp + wn * 32 + p * 16 + bColSel) * 2);
                bf[2 * p][0] = tmp[0]; bf[2 * p][1] = tmp[1];
                bf[2 * p + 1][0] = tmp[2]; bf[2 * p + 1][1] = tmp[3];
            }
#pragma unroll
            for (int mi = 0; mi < MI; mi++)
#pragma unroll
                for (int nj = 0; nj < 4; nj++)
                    mma16(acc[mi][nj], af[mi], bf[nj]);
        }
    }

    // ---- epilogue (all-half I/O) ----
#pragma unroll
    for (int mi = 0; mi < MI; mi++) {
        const long long m0 = bm + wm * (MI * 16) + mi * 16 + gid;
#pragma unroll
        for (int nj = 0; nj < 4; nj++) {
            const long long n0 = bn + wn * 32 + nj * 8 + tig * 2;
            float2 bb = make_float2(0.0f, 0.0f);
            if (bptr) bb = *reinterpret_cast<const float2*>(bptr + n0);

            float2 o0, o1;
            o0.x = acc[mi][nj][0] + bb.x;
            o0.y = acc[mi][nj][1] + bb.y;
            o1.x = acc[mi][nj][2] + bb.x;
            o1.y = acc[mi][nj][3] + bb.y;
            if (EPI == 1) {
                o0.x = fmaxf(o0.x, 0.0f); o0.y = fmaxf(o0.y, 0.0f);
                o1.x = fmaxf(o1.x, 0.0f); o1.y = fmaxf(o1.y, 0.0f);
            }
            if (EPI == 2) {
                __half2 r0 = *reinterpret_cast<const __half2*>(res + m0 * ldc + n0);
                __half2 r1 = *reinterpret_cast<const __half2*>(res + (m0 + 8) * ldc + n0);
                o0.x += __low2float(r0); o0.y += __high2float(r0);
                o1.x += __low2float(r1); o1.y += __high2float(r1);
            }
            __half* c = Chsel + cOff;
            *reinterpret_cast<__half2*>(c + m0 * ldc + n0) = __floats2half2_rn(o0.x, o0.y);
            *reinterpret_cast<__half2*>(c + (m0 + 8) * ldc + n0) = __floats2half2_rn(o1.x, o1.y);
        }
    }
}

// =====================================================================
// Fused flash attention (fp16 mma + ldmatrix, fp32 softmax/accum).
//   O[z] = softmax(Q[z] @ K[z]^T / 8) @ V[z]
// P stays in REGISTERS (C->A fragment coincidence). Verified Round 14.
// =====================================================================
__global__ void __launch_bounds__(256, 2)
flash_h(const __half* __restrict__ Q, const __half* __restrict__ K,
        const __half* __restrict__ V, __half* __restrict__ Och)
{
    constexpr int PW = 72;                     // padded row stride (halves)
    constexpr int STG = 3;
    constexpr int QP_H = 128 * PW;
    constexpr int KV_H = 64 * PW;
    constexpr int T = S_ / 64;                 // 32 key tiles

    extern __shared__ __half smh[];
    __half* sQP = smh;                         // Q staging only
    __half* sK  = smh + QP_H;                  // [STG][64 keys][PW]
    __half* sV  = sK + STG * KV_H;             // [STG][64 keys][PW]
    const uint32_t uK  = smem_u32(sK);
    const uint32_t uV  = smem_u32(sV);

    const int tid  = threadIdx.x;
    const int wid  = tid >> 5;
    const int lane = tid & 31;
    const int gid  = lane >> 2;
    const int tig  = lane & 3;
    const int wr   = wid * 16;

    const int z  = blockIdx.y;
    const int zb = z / H_;
    const int zh = z % H_;
    const long long m0 = (long long)blockIdx.x * 128;

    const __half* Qz = Q + (long long)z * S_ * DK_;
    const __half* Kz = K + (long long)z * S_ * DK_;
    const __half* Vz = V + (long long)z * S_ * DK_;

    // ---- stage Q tile [128][64] ----
#pragma unroll
    for (int i = 0; i < 4; i++) {
        int e = tid + i * 256;
        int r = e >> 3, c = e & 7;
        *reinterpret_cast<uint4*>(&sQP[r * PW + c * 8]) =
            *reinterpret_cast<const uint4*>(Qz + (m0 + r) * DK_ + c * 8);
    }
    __syncthreads();

    // ---- Q fragments, scaled by exact 0.125 ----
    const __half2 sc8 = __float2half2_rn(0.125f);
    uint32_t qf[4][4];
#pragma unroll
    for (int ks = 0; ks < 4; ks++) {
        const __half* qp = sQP + (wr + gid) * PW + ks * 16 + 2 * tig;
        qf[ks][0] = h2scale(ldh2(qp), sc8);
        qf[ks][1] = h2scale(ldh2(qp + 8 * PW), sc8);
        qf[ks][2] = h2scale(ldh2(qp + 8), sc8);
        qf[ks][3] = h2scale(ldh2(qp + 8 * PW + 8), sc8);
    }

    float oacc[8][4];
#pragma unroll
    for (int nj = 0; nj < 8; nj++)
#pragma unroll
        for (int r = 0; r < 4; r++) oacc[nj][r] = 0.0f;
    float mrow0 = -1e30f, mrow1 = -1e30f;
    float lrow0 = 0.0f,  lrow1 = 0.0f;

    auto stage = [&](int t) {
        const int buf = t % STG;
        const uint32_t kDst = uK + (uint32_t)buf * KV_H * 2;
        const uint32_t vDst = uV + (uint32_t)buf * KV_H * 2;
#pragma unroll
        for (int i = 0; i < 2; i++) {
            int e = tid + i * 256;
            int r = e >> 3, c = e & 7;
            cp16(kDst + (uint32_t)(r * PW + c * 8) * 2,
                 Kz + (long long)(t * 64 + r) * DK_ + c * 8);
        }
#pragma unroll
        for (int i = 0; i < 2; i++) {
            int e = tid + i * 256;
            int r = e >> 3, c = e & 7;
            cp16(vDst + (uint32_t)(r * PW + c * 8) * 2,
                 Vz + (long long)(t * 64 + r) * DK_ + c * 8);
        }
        asm volatile("cp.async.commit_group;" ::: "memory");
    };

    // ldmatrix lane-address components
    const int nRowSel = (lane >> 4) * 8 + (lane & 7);       // non-trans: row within 16
    const int nColSel = ((lane >> 3) & 1) * 8;              // non-trans: k sub-offset
    const int tRowSel = (lane & 7) + ((lane >> 3) & 1) * 8; // trans: k row within 16
    const int tColSel = (lane >> 4) * 8;                    // trans: n sub-offset

    stage(0);
    stage(1);
    for (int t = 0; t < T; t++) {
        if (t + 2 < T) {
            asm volatile("cp.async.wait_group 1;" ::: "memory");
        } else {
            asm volatile("cp.async.wait_group 0;" ::: "memory");
        }
        __syncthreads();                    // tile t published; iter t-1 readers done
        if (t + 2 < T) stage(t + 2);        // overwrites buffer (t-1)%3 — safe

        const uint32_t uKs = uK + (uint32_t)(t % STG) * KV_H * 2;
        const uint32_t uVs = uV + (uint32_t)(t % STG) * KV_H * 2;

        // ---- S = (Q/8) @ K^T : 16 x 64 per warp ----
        float sacc[8][4];
#pragma unroll
        for (int nj = 0; nj < 8; nj++)
#pragma unroll
            for (int r = 0; r < 4; r++) sacc[nj][r] = 0.0f;
#pragma unroll
        for (int ks = 0; ks < 4; ks++) {
            const int kc = ks * 16;
#pragma unroll
            for (int p = 0; p < 4; p++) {
                uint32_t tmp[4];
                ldsm4(tmp, uKs + (uint32_t)((p * 16 + nRowSel) * PW + kc + nColSel) * 2);
                mma16(sacc[2 * p], qf[ks], tmp);
                mma16(sacc[2 * p + 1], qf[ks], tmp + 2);
            }
        }

        // ---- online softmax (P packed to registers) ----
        float mx0 = -1e30f, mx1 = -1e30f;
#pragma unroll
        for (int nj = 0; nj < 8; nj++) {
            mx0 = fmaxf(mx0, fmaxf(sacc[nj][0], sacc[nj][1]));
            mx1 = fmaxf(mx1, fmaxf(sacc[nj][2], sacc[nj][3]));
        }
        mx0 = fmaxf(mx0, __shfl_xor_sync(0xffffffffu, mx0, 1));
        mx0 = fmaxf(mx0, __shfl_xor_sync(0xffffffffu, mx0, 2));
        mx1 = fmaxf(mx1, __shfl_xor_sync(0xffffffffu, mx1, 1));
        mx1 = fmaxf(mx1, __shfl_xor_sync(0xffffffffu, mx1, 2));

        const float mn0 = fmaxf(mrow0, mx0);
        const float mn1 = fmaxf(mrow1, mx1);
        const float sc0 = __expf(mrow0 - mn0);
        const float sc1 = __expf(mrow1 - mn1);
        mrow0 = mn0; mrow1 = mn1;

        uint32_t puint[16];
        float ls0 = 0.0f, ls1 = 0.0f;
#pragma unroll
        for (int nj = 0; nj < 8; nj++) {
            float e0 = __expf(sacc[nj][0] - mn0);
            float e1 = __expf(sacc[nj][1] - mn0);
            float e2 = __expf(sacc[nj][2] - mn1);
            float e3 = __expf(sacc[nj][3] - mn1);
            ls0 += e0 + e1;
            ls1 += e2 + e3;
            puint[2 * nj]     = packh2(e0, e1);
            puint[2 * nj + 1] = packh2(e2, e3);
        }
        ls0 += __shfl_xor_sync(0xffffffffu, ls0, 1);
        ls0 += __shfl_xor_sync(0xffffffffu, ls0, 2);
        ls1 += __shfl_xor_sync(0xffffffffu, ls1, 1);
        ls1 += __shfl_xor_sync(0xffffffffu, ls1, 2);
        lrow0 = lrow0 * sc0 + ls0;
        lrow1 = lrow1 * sc1 + ls1;

#pragma unroll
        for (int nj = 0; nj < 8; nj++) {
            oacc[nj][0] *= sc0; oacc[nj][1] *= sc0;
            oacc[nj][2] *= sc1; oacc[nj][3] *= sc1;
        }

        // ---- O += P @ V  (P from registers; V [keys][dk] via trans) ----
#pragma unroll
        for (int ks = 0; ks < 4; ks++) {
            const int kc = ks * 16;
            uint32_t pf[4] = {puint[4 * ks], puint[4 * ks + 1],
                              puint[4 * ks + 2], puint[4 * ks + 3]};
#pragma unroll
            for (int p = 0; p < 4; p++) {
                uint32_t tmp[4];
                ldsm4t(tmp, uVs + (uint32_t)((kc + tRowSel) * PW + p * 16 + tColSel) * 2);
                mma16(oacc[2 * p], pf, tmp);
                mma16(oacc[2 * p + 1], pf, tmp + 2);
            }
        }
    }

    // ---- epilogue: normalize, write half into concat layout ----
    const float inv0 = 1.0f / lrow0;
    const float inv1 = 1.0f / lrow1;
    const long long row0 = (long long)zb * S_ + m0 + wr + gid;
    const long long row1 = row0 + 8;
    __half* o0 = Och + row0 * D_ + zh * DK_;
    __half* o1 = Och + row1 * D_ + zh * DK_;
#pragma unroll
    for (int nj = 0; nj < 8; nj++) {
        const int c = nj * 8 + tig * 2;
        *reinterpret_cast<__half2*>(o0 + c) =
            __floats2half2_rn(oacc[nj][0] * inv0, oacc[nj][1] * inv0);
        *reinterpret_cast<__half2*>(o1 + c) =
            __floats2half2_rn(oacc[nj][2] * inv1, oacc[nj][3] * inv1);
    }
}

// =====================================================================
// Segmented fp32 -> fp16 conversion (one launch for x + all weights).
// =====================================================================
struct CvtSeg { const float* src; __half* dst; int nblk; };
struct CvtArgs { CvtSeg s[7]; };

__global__ void __launch_bounds__(256)
f2h_all(CvtArgs a)
{
    int b = blockIdx.x;
#pragma unroll
    for (int i = 0; i < 7; i++) {
        if (b < a.s[i].nblk) {
            const float4* src = reinterpret_cast<const float4*>(a.s[i].src);
            uint2* dst = reinterpret_cast<uint2*>(a.s[i].dst);
            int e = b * 256 + threadIdx.x;
            float4 v = src[e];
            __half2 lo = __floats2half2_rn(v.x, v.y);
            __half2 hi = __floats2half2_rn(v.z, v.w);
            uint2 o;
            o.x = *reinterpret_cast<uint32_t*>(&lo);
            o.y = *reinterpret_cast<uint32_t*>(&hi);
            dst[e] = o;
            return;
        }
        b -= a.s[i].nblk;
    }
}

// =====================================================================
// Row LayerNorm, HALF input, 2 rows per 256-thread block.
// Each 128-thread half handles one row (math per row identical to the
// 1-row kernel). Writes fp32 out and/or half outh.
// =====================================================================
__global__ void __launch_bounds__(256)
layernorm_h2(const __half* __restrict__ in, const float* __restrict__ g,
             const float* __restrict__ b, float* __restrict__ outf,
             __half* __restrict__ outh)
{
    const int tid  = threadIdx.x;
    const int rsel = tid >> 7;                 // 0 or 1: which row
    const int rtid = tid & 127;                // thread within row
    const long long row = (long long)blockIdx.x * 2 + rsel;

    const uint2 hv = reinterpret_cast<const uint2*>(in + row * D_)[rtid];
    __half2 h01 = *reinterpret_cast<const __half2*>(&hv.x);
    __half2 h23 = *reinterpret_cast<const __half2*>(&hv.y);
    float4 v;
    v.x = __low2float(h01); v.y = __high2float(h01);
    v.z = __low2float(h23); v.w = __high2float(h23);

    float s  = v.x + v.y + v.z + v.w;
    float sq = v.x * v.x + v.y * v.y + v.z * v.z + v.w * v.w;
#pragma unroll
    for (int o = 16; o; o >>= 1) {
        s  += __shfl_xor_sync(0xffffffffu, s, o);
        sq += __shfl_xor_sync(0xffffffffu, sq, o);
    }
    __shared__ float ssum[8], ssq[8];          // 8 warps total (4 per row)
    if ((tid & 31) == 0) { ssum[tid >> 5] = s; ssq[tid >> 5] = sq; }
    __syncthreads();
    const int wb = rsel * 4;
    s  = ssum[wb] + ssum[wb + 1] + ssum[wb + 2] + ssum[wb + 3];
    sq = ssq[wb] + ssq[wb + 1] + ssq[wb + 2] + ssq[wb + 3];

    const float mu  = s * (1.0f / D_);
    float var = sq * (1.0f / D_) - mu * mu;
    var = fmaxf(var, 0.0f);
    const float rstd = rsqrtf(var + 1e-5f);

    float4 gg = reinterpret_cast<const float4*>(g)[rtid];
    float4 bb = reinterpret_cast<const float4*>(b)[rtid];
    float4 o4;
    o4.x = (v.x - mu) * rstd * gg.x + bb.x;
    o4.y = (v.y - mu) * rstd * gg.y + bb.y;
    o4.z = (v.z - mu) * rstd * gg.z + bb.z;
    o4.w = (v.w - mu) * rstd * gg.w + bb.w;
    if (outf != nullptr)
        reinterpret_cast<float4*>(outf + row * D_)[rtid] = o4;
    if (outh != nullptr) {
        __half2 lo = __floats2half2_rn(o4.x, o4.y);
        __half2 hi = __floats2half2_rn(o4.z, o4.w);
        uint2 o;
        o.x = *reinterpret_cast<uint32_t*>(&lo);
        o.y = *reinterpret_cast<uint32_t*>(&hi);
        reinterpret_cast<uint2*>(outh + row * D_)[rtid] = o;
    }
}

// =====================================================================
// Launcher
// =====================================================================
static constexpr int SMEM_M4N64  = 3 * (128 * 72 + 64 * 72) * 2;     // 82944
static constexpr int SMEM_M2N64  = 3 * (64 * 72 + 64 * 72) * 2;      // 55296
static constexpr int SMEM_M4N128 = 3 * (128 * 72 + 64 * 136) * 2;    // 107520
static constexpr int SMEM_FLASH  = (128 * 72 + 6 * 64 * 72) * 2;     // 73728

extern "C" void kernel_launch(void* const* d_in, const int* in_sizes, int n_in,
                              void* d_out, int out_size)
{
    (void)in_sizes; (void)n_in; (void)out_size;
    const float* x     = (const float*)d_in[0];
    const float* Wq    = (const float*)d_in[1];
    const float* bq    = (const float*)d_in[2];
    const float* Wk    = (const float*)d_in[3];
    const float* bk    = (const float*)d_in[4];
    const float* Wv    = (const float*)d_in[5];
    const float* bv    = (const float*)d_in[6];
    const float* Wo    = (const float*)d_in[7];
    const float* bo    = (const float*)d_in[8];
    const float* ln1_g = (const float*)d_in[9];
    const float* ln1_b = (const float*)d_in[10];
    const float* W1    = (const float*)d_in[11];
    const float* b1    = (const float*)d_in[12];
    const float* W2    = (const float*)d_in[13];
    const float* b2    = (const float*)d_in[14];
    const float* ln2_g = (const float*)d_in[15];
    const float* ln2_b = (const float*)d_in[16];
    float* out = (float*)d_out;

    __half *xh, *q, *k, *v, *och, *h1h, *hh, *ff, *h2h;
    __half *Wqh, *Wkh, *Wvh, *Woh, *W1h, *W2h;
    cudaGetSymbolAddress((void**)&xh,  g_xh);
    cudaGetSymbolAddress((void**)&q,   g_q);
    cudaGetSymbolAddress((void**)&k,   g_k);
    cudaGetSymbolAddress((void**)&v,   g_v);
    cudaGetSymbolAddress((void**)&och, g_och);
    cudaGetSymbolAddress((void**)&h1h, g_h1h);
    cudaGetSymbolAddress((void**)&hh,  g_hh);
    cudaGetSymbolAddress((void**)&ff,  g_ff);
    cudaGetSymbolAddress((void**)&h2h, g_h2h);
    cudaGetSymbolAddress((void**)&Wqh, g_Wqh);
    cudaGetSymbolAddress((void**)&Wkh, g_Wkh);
    cudaGetSymbolAddress((void**)&Wvh, g_Wvh);
    cudaGetSymbolAddress((void**)&Woh, g_Woh);
    cudaGetSymbolAddress((void**)&W1h, g_W1h);
    cudaGetSymbolAddress((void**)&W2h, g_W2h);

    cudaFuncSetAttribute(gemm_h<4, 64, 0, true>,   cudaFuncAttributeMaxDynamicSharedMemorySize, SMEM_M4N64);
    cudaFuncSetAttribute(gemm_h<2, 64, 2, false>,  cudaFuncAttributeMaxDynamicSharedMemorySize, SMEM_M2N64);
    cudaFuncSetAttribute(gemm_h<4, 128, 1, false>, cudaFuncAttributeMaxDynamicSharedMemorySize, SMEM_M4N128);
    cudaFuncSetAttribute(flash_h,                  cudaFuncAttributeMaxDynamicSharedMemorySize, SMEM_FLASH);

    const Off lin0      = {1, 0, 0};
    const Off oA_qkv    = {H_, (long long)S_ * D_, 0};
    const Off oB_qkv    = {H_, 0, (long long)D_ * DK_};
    const Off oBias_qkv = {H_, 0, (long long)DK_};
    const Off oC_qkv    = {1, (long long)S_ * DK_, 0};

    // ---- 0. one-shot fp32->fp16 conversion ----
    CvtArgs ca;
    ca.s[0] = {x,  xh,  (int)((long long)M_ * D_ / 1024)};
    ca.s[1] = {Wq, Wqh, (int)((long long)H_ * D_ * DK_ / 1024)};
    ca.s[2] = {Wk, Wkh, (int)((long long)H_ * D_ * DK_ / 1024)};
    ca.s[3] = {Wv, Wvh, (int)((long long)H_ * D_ * DK_ / 1024)};
    ca.s[4] = {Wo, Woh, (int)((long long)D_ * D_ / 1024)};
    ca.s[5] = {W1, W1h, (int)((long long)D_ * DF_ / 1024)};
    ca.s[6] = {W2, W2h, (int)((long long)DF_ * D_ / 1024)};
    int totBlk = 0;
    for (int i = 0; i < 7; i++) totBlk += ca.s[i].nblk;
    f2h_all<<<totBlk, 256>>>(ca);

    // ---- 1. merged QKV projections (BM=128, BK=64, T=8) ----
    gemm_h<4, 64, 0, true><<<dim3(3, 16, B_ * H_), 128, SMEM_M4N64>>>(
        xh, Wqh, Wkh, Wvh, bq, bk, bv, nullptr, q, k, v,
        S_, DK_, D_, DK_, oA_qkv, oB_qkv, oBias_qkv, oC_qkv);

    // ---- 2. fused flash attention -> half concat layout ----
    flash_h<<<dim3(S_ / 128, B_ * H_), 256, SMEM_FLASH>>>(q, k, v, och);

    // ---- 3. h1h = xh + och @ Wo + bo  (half residual, half out) ----
    gemm_h<2, 64, 2, false><<<dim3(8, 64, 1), 128, SMEM_M2N64>>>(
        och, Woh, Woh, Woh, bo, bo, bo, xh, h1h, h1h, h1h,
        M_, D_, D_, D_, lin0, lin0, lin0, lin0);

    // ---- 4. hh = LN1(h1h)  (half in, half out only; 2 rows/block) ----
    layernorm_h2<<<M_ / 2, 256>>>(h1h, ln1_g, ln1_b, nullptr, hh);

    // ---- 5. ff = relu(hh @ W1 + b1)  (BM=128, BN=128) ----
    gemm_h<4, 128, 1, false><<<dim3(16, 32, 1), 256, SMEM_M4N128>>>(
        hh, W1h, W1h, W1h, b1, b1, b1, nullptr, ff, ff, ff,
        M_, DF_, D_, DF_, lin0, lin0, lin0, lin0);

    // ---- 6. h2h = hh + ff @ W2 + b2  (half residual, half out) ----
    gemm_h<2, 64, 2, false><<<dim3(8, 64, 1), 128, SMEM_M2N64>>>(
        ff, W2h, W2h, W2h, b2, b2, b2, hh, h2h, h2h, h2h,
        M_, D_, DF_, D_, lin0, lin0, lin0, lin0);

    // ---- 7. out = LN2(h2h)  (half in, fp32 out; 2 rows/block) ----
    layernorm_h2<<<M_ / 2, 256>>>(h2h, ln2_g, ln2_b, out, nullptr);
}

// round 17
// speedup vs baseline: 1.1363x; 1.0210x over previous
#include <cuda_runtime.h>
#include <cuda_fp16.h>
#include <cstdint>
#include <math.h>

// Problem constants
static constexpr int B_  = 2;
static constexpr int S_  = 2048;
static constexpr int D_  = 512;
static constexpr int H_  = 8;
static constexpr int DK_ = 64;
static constexpr int DF_ = 2048;
static constexpr int M_  = B_ * S_;
static constexpr long long QKV_ELEMS = (long long)B_ * H_ * S_ * DK_;

// -------- scratch (device globals; no allocation allowed) --------
__device__ __half g_xh [(long long)M_ * D_];
__device__ __half g_q  [QKV_ELEMS];
__device__ __half g_k  [QKV_ELEMS];
__device__ __half g_v  [QKV_ELEMS];
__device__ __half g_och[(long long)M_ * D_];
__device__ __half g_h1h[(long long)M_ * D_];
__device__ __half g_hh [(long long)M_ * D_];
__device__ __half g_ff [(long long)M_ * DF_];
__device__ __half g_h2h[(long long)M_ * D_];
__device__ __half g_Wqh[(long long)H_ * D_ * DK_];   // [h][512][64]  (natural [K,N])
__device__ __half g_Wkh[(long long)H_ * D_ * DK_];
__device__ __half g_Wvh[(long long)H_ * D_ * DK_];
__device__ __half g_Woh[(long long)D_ * D_];         // [512][512]
__device__ __half g_W1h[(long long)D_ * DF_];        // [512][2048]
__device__ __half g_W2h[(long long)DF_ * D_];        // [2048][512]

// -------- batched offset descriptor --------
struct Off { int div; long long s1; long long s2; };
__device__ __forceinline__ long long offz(Off o, int z) {
    return (long long)(z / o.div) * o.s1 + (long long)(z % o.div) * o.s2;
}

// ===================== PTX helpers =====================
__device__ __forceinline__ uint32_t smem_u32(const void* p) {
    uint32_t a;
    asm("{ .reg .u64 t; cvta.to.shared.u64 t, %1; cvt.u32.u64 %0, t; }" : "=r"(a) : "l"(p));
    return a;
}
__device__ __forceinline__ void cp16(uint32_t dst, const void* src) {
    asm volatile("cp.async.cg.shared.global [%0], [%1], 16;"
                 :: "r"(dst), "l"(__cvta_generic_to_global(src)) : "memory");
}
__device__ __forceinline__ void mma16(float* d, const uint32_t* a, const uint32_t* b) {
    asm volatile(
        "mma.sync.aligned.m16n8k16.row.col.f32.f16.f16.f32 "
        "{%0,%1,%2,%3}, {%4,%5,%6,%7}, {%8,%9}, {%0,%1,%2,%3};"
        : "+f"(d[0]), "+f"(d[1]), "+f"(d[2]), "+f"(d[3])
        : "r"(a[0]), "r"(a[1]), "r"(a[2]), "r"(a[3]), "r"(b[0]), "r"(b[1]));
}
__device__ __forceinline__ void ldsm4(uint32_t* r, uint32_t a) {
    asm volatile("ldmatrix.sync.aligned.m8n8.x4.shared.b16 {%0,%1,%2,%3}, [%4];"
                 : "=r"(r[0]), "=r"(r[1]), "=r"(r[2]), "=r"(r[3]) : "r"(a));
}
__device__ __forceinline__ void ldsm4t(uint32_t* r, uint32_t a) {
    asm volatile("ldmatrix.sync.aligned.m8n8.x4.trans.shared.b16 {%0,%1,%2,%3}, [%4];"
                 : "=r"(r[0]), "=r"(r[1]), "=r"(r[2]), "=r"(r[3]) : "r"(a));
}
__device__ __forceinline__ uint32_t ldh2(const __half* p) {
    return *reinterpret_cast<const uint32_t*>(p);
}
__device__ __forceinline__ uint32_t h2scale(uint32_t x, __half2 s) {
    __half2 v = __hmul2(*reinterpret_cast<__half2*>(&x), s);
    return *reinterpret_cast<uint32_t*>(&v);
}
__device__ __forceinline__ uint32_t packh2(float a, float b) {
    __half2 h = __floats2half2_rn(a, b);
    return *reinterpret_cast<uint32_t*>(&h);
}

// =====================================================================
// fp16 mma GEMM, B in NATURAL [K,N] row-major layout (trans ldmatrix).
//   C = A @ B (+bias)(+relu|+residual)   — ALL I/O half (accum fp32)
// A half row-major [M,K]. BM = 32*MI, BK=64, BN in {64,128}.
// STG-stage cp.async pipeline (2 or 3), one barrier per iteration.
//   STG=3: wait_group 1 (or 0 at tail); stage(t+2) after barrier.
//   STG=2: wait_group 0; stage(t+1) after barrier (overwrites buffer
//          read at t-1, whose readers passed the barrier).
// EPI: 0 bias; 1 bias+relu; 2 bias+half-residual. Output always half.
// MULTI: blockIdx.x selects (B, bias, Ch) triple, bn = 0.
// =====================================================================
template<int MI, int BN, int STG, int EPI, bool MULTI>
__global__ void __launch_bounds__(2 * (BN / 32) * 32,
                                  (MI == 2 || STG == 2) ? 4 : 2)
gemm_h(const __half* __restrict__ A,
       const __half* __restrict__ B0, const __half* __restrict__ B1, const __half* __restrict__ B2,
       const float* __restrict__ g0, const float* __restrict__ g1, const float* __restrict__ g2,
       const __half* __restrict__ res,
       __half* __restrict__ Ch0, __half* __restrict__ Ch1, __half* __restrict__ Ch2,
       int M, int N, int K, int ldc,
       Off oA, Off oB, Off oBias, Off oC)
{
    constexpr int BM = 32 * MI;
    constexpr int BK = 64;
    constexpr int SW = 72;                        // A smem row stride (halves)
    constexpr int BWp = BN + 8;                   // B smem row stride (halves)
    constexpr int NWN = BN / 32;
    constexpr int NT  = 2 * NWN * 32;             // 128 or 256 threads
    constexpr int A_H = BM * SW;
    constexpr int B_H = BK * BWp;
    constexpr int A_ITERS = (BM * (BK / 8)) / NT;
    constexpr int B_ITERS = (BK * (BN / 8)) / NT;
    constexpr int BCH = BN / 8;                   // 16B chunks per B row

    extern __shared__ __half smh[];
    __half* sA = smh;                 // [STG][BM][SW]
    __half* sB = smh + STG * A_H;     // [STG][BK][BWp]
    const uint32_t uA = smem_u32(sA);
    const uint32_t uB = smem_u32(sB);

    const int tid  = threadIdx.x;
    const int wid  = tid >> 5;
    const int lane = tid & 31;
    const int gid  = lane >> 2;
    const int tig  = lane & 3;
    const int wn   = wid % NWN;
    const int wm   = wid / NWN;
    const int z    = blockIdx.z;
    const int sel  = MULTI ? blockIdx.x : 0;

    const __half* Bsel = (sel == 0) ? B0 : (sel == 1 ? B1 : B2);
    const float*  gsel = (sel == 0) ? g0 : (sel == 1 ? g1 : g2);
    __half*       Chsel = (sel == 0) ? Ch0 : (sel == 1 ? Ch1 : Ch2);

    const __half* Am = A + offz(oA, z);
    Bsel += offz(oB, z);
    const long long cOff = offz(oC, z);
    const float* bptr = (gsel != nullptr) ? gsel + offz(oBias, z) : nullptr;

    const long long bm = (long long)blockIdx.y * BM;
    const long long bn = MULTI ? 0 : (long long)blockIdx.x * BN;
    const int T = K / BK;

    const __half* aBase = Am + bm * K;
    const __half* bBase = Bsel + bn;              // [K,N]: row stride N

    auto stage = [&](int t) {
        const int buf = t % STG;
        const __half* aSrc = aBase + (long long)t * BK;
        const __half* bSrc = bBase + (long long)t * BK * N;
        const uint32_t aDst = uA + (uint32_t)buf * A_H * 2;
        const uint32_t bDst = uB + (uint32_t)buf * B_H * 2;
#pragma unroll
        for (int i = 0; i < A_ITERS; i++) {
            int e = tid + i * NT;
            int r = e >> 3, c = e & 7;            // 8 chunks of 8 halves per 64-half row
            cp16(aDst + (uint32_t)(r * SW + c * 8) * 2, aSrc + (long long)r * K + c * 8);
        }
#pragma unroll
        for (int i = 0; i < B_ITERS; i++) {
            int e = tid + i * NT;
            int r = e / BCH, c = e % BCH;
            cp16(bDst + (uint32_t)(r * BWp + c * 8) * 2, bSrc + (long long)r * N + c * 8);
        }
        asm volatile("cp.async.commit_group;" ::: "memory");
    };

    float acc[MI][4][4];
#pragma unroll
    for (int i = 0; i < MI; i++)
#pragma unroll
        for (int j = 0; j < 4; j++)
#pragma unroll
            for (int r = 0; r < 4; r++) acc[i][j][r] = 0.0f;

    // ldmatrix lane-address components
    const int aRow = (lane & 7) + ((lane >> 3) & 1) * 8;
    const int aColSel = (lane >> 4) * 8;
    const int bRowSel = (lane & 7) + ((lane >> 3) & 1) * 8;  // k within tile
    const int bColSel = (lane >> 4) * 8;                      // n sub-offset

    stage(0);
    if (STG == 3 && T > 1) stage(1);
    for (int t = 0; t < T; t++) {
        if (STG == 3) {
            if (t + 2 < T) {
                asm volatile("cp.async.wait_group 1;" ::: "memory");
            } else {
                asm volatile("cp.async.wait_group 0;" ::: "memory");
            }
        } else {
            asm volatile("cp.async.wait_group 0;" ::: "memory");
        }
        __syncthreads();                    // buffer t published; iter t-1 readers done
        if (STG == 3) {
            if (t + 2 < T) stage(t + 2);    // overwrites buffer (t-1)%3 — safe
        } else {
            if (t + 1 < T) stage(t + 1);    // overwrites buffer (t-1)%2 — safe
        }

        const uint32_t uAs = uA + (uint32_t)(t % STG) * A_H * 2;
        const uint32_t uBs = uB + (uint32_t)(t % STG) * B_H * 2;
#pragma unroll
        for (int ks = 0; ks < BK / 16; ks++) {
            const int kc = ks * 16;
            uint32_t af[MI][4];
#pragma unroll
            for (int mi = 0; mi < MI; mi++)
                ldsm4(af[mi], uAs + (uint32_t)((wm * (MI * 16) + mi * 16 + aRow) * SW + kc + aColSel) * 2);
            uint32_t bf[4][2];
#pragma unroll
            for (int p = 0; p < 2; p++) {
                uint32_t tmp[4];
                ldsm4t(tmp, uBs + (uint32_t)((kc + bRowSel) * BWp + wn * 32 + p * 16 + bColSel) * 2);
                bf[2 * p][0] = tmp[0]; bf[2 * p][1] = tmp[1];
                bf[2 * p + 1][0] = tmp[2]; bf[2 * p + 1][1] = tmp[3];
            }
#pragma unroll
            for (int mi = 0; mi < MI; mi++)
#pragma unroll
                for (int nj = 0; nj < 4; nj++)
                    mma16(acc[mi][nj], af[mi], bf[nj]);
        }
    }

    // ---- epilogue (all-half I/O) ----
#pragma unroll
    for (int mi = 0; mi < MI; mi++) {
        const long long m0 = bm + wm * (MI * 16) + mi * 16 + gid;
#pragma unroll
        for (int nj = 0; nj < 4; nj++) {
            const long long n0 = bn + wn * 32 + nj * 8 + tig * 2;
            float2 bb = make_float2(0.0f, 0.0f);
            if (bptr) bb = *reinterpret_cast<const float2*>(bptr + n0);

            float2 o0, o1;
            o0.x = acc[mi][nj][0] + bb.x;
            o0.y = acc[mi][nj][1] + bb.y;
            o1.x = acc[mi][nj][2] + bb.x;
            o1.y = acc[mi][nj][3] + bb.y;
            if (EPI == 1) {
                o0.x = fmaxf(o0.x, 0.0f); o0.y = fmaxf(o0.y, 0.0f);
                o1.x = fmaxf(o1.x, 0.0f); o1.y = fmaxf(o1.y, 0.0f);
            }
            if (EPI == 2) {
                __half2 r0 = *reinterpret_cast<const __half2*>(res + m0 * ldc + n0);
                __half2 r1 = *reinterpret_cast<const __half2*>(res + (m0 + 8) * ldc + n0);
                o0.x += __low2float(r0); o0.y += __high2float(r0);
                o1.x += __low2float(r1); o1.y += __high2float(r1);
            }
            __half* c = Chsel + cOff;
            *reinterpret_cast<__half2*>(c + m0 * ldc + n0) = __floats2half2_rn(o0.x, o0.y);
            *reinterpret_cast<__half2*>(c + (m0 + 8) * ldc + n0) = __floats2half2_rn(o1.x, o1.y);
        }
    }
}

// =====================================================================
// Fused flash attention (fp16 mma + ldmatrix, fp32 softmax/accum).
//   O[z] = softmax(Q[z] @ K[z]^T / 8) @ V[z]
// P stays in REGISTERS (C->A fragment coincidence). Verified Round 14.
// =====================================================================
__global__ void __launch_bounds__(256, 2)
flash_h(const __half* __restrict__ Q, const __half* __restrict__ K,
        const __half* __restrict__ V, __half* __restrict__ Och)
{
    constexpr int PW = 72;                     // padded row stride (halves)
    constexpr int STG = 3;
    constexpr int QP_H = 128 * PW;
    constexpr int KV_H = 64 * PW;
    constexpr int T = S_ / 64;                 // 32 key tiles

    extern __shared__ __half smh[];
    __half* sQP = smh;                         // Q staging only
    __half* sK  = smh + QP_H;                  // [STG][64 keys][PW]
    __half* sV  = sK + STG * KV_H;             // [STG][64 keys][PW]
    const uint32_t uK  = smem_u32(sK);
    const uint32_t uV  = smem_u32(sV);

    const int tid  = threadIdx.x;
    const int wid  = tid >> 5;
    const int lane = tid & 31;
    const int gid  = lane >> 2;
    const int tig  = lane & 3;
    const int wr   = wid * 16;

    const int z  = blockIdx.y;
    const int zb = z / H_;
    const int zh = z % H_;
    const long long m0 = (long long)blockIdx.x * 128;

    const __half* Qz = Q + (long long)z * S_ * DK_;
    const __half* Kz = K + (long long)z * S_ * DK_;
    const __half* Vz = V + (long long)z * S_ * DK_;

    // ---- stage Q tile [128][64] ----
#pragma unroll
    for (int i = 0; i < 4; i++) {
        int e = tid + i * 256;
        int r = e >> 3, c = e & 7;
        *reinterpret_cast<uint4*>(&sQP[r * PW + c * 8]) =
            *reinterpret_cast<const uint4*>(Qz + (m0 + r) * DK_ + c * 8);
    }
    __syncthreads();

    // ---- Q fragments, scaled by exact 0.125 ----
    const __half2 sc8 = __float2half2_rn(0.125f);
    uint32_t qf[4][4];
#pragma unroll
    for (int ks = 0; ks < 4; ks++) {
        const __half* qp = sQP + (wr + gid) * PW + ks * 16 + 2 * tig;
        qf[ks][0] = h2scale(ldh2(qp), sc8);
        qf[ks][1] = h2scale(ldh2(qp + 8 * PW), sc8);
        qf[ks][2] = h2scale(ldh2(qp + 8), sc8);
        qf[ks][3] = h2scale(ldh2(qp + 8 * PW + 8), sc8);
    }

    float oacc[8][4];
#pragma unroll
    for (int nj = 0; nj < 8; nj++)
#pragma unroll
        for (int r = 0; r < 4; r++) oacc[nj][r] = 0.0f;
    float mrow0 = -1e30f, mrow1 = -1e30f;
    float lrow0 = 0.0f,  lrow1 = 0.0f;

    auto stage = [&](int t) {
        const int buf = t % STG;
        const uint32_t kDst = uK + (uint32_t)buf * KV_H * 2;
        const uint32_t vDst = uV + (uint32_t)buf * KV_H * 2;
#pragma unroll
        for (int i = 0; i < 2; i++) {
            int e = tid + i * 256;
            int r = e >> 3, c = e & 7;
            cp16(kDst + (uint32_t)(r * PW + c * 8) * 2,
                 Kz + (long long)(t * 64 + r) * DK_ + c * 8);
        }
#pragma unroll
        for (int i = 0; i < 2; i++) {
            int e = tid + i * 256;
            int r = e >> 3, c = e & 7;
            cp16(vDst + (uint32_t)(r * PW + c * 8) * 2,
                 Vz + (long long)(t * 64 + r) * DK_ + c * 8);
        }
        asm volatile("cp.async.commit_group;" ::: "memory");
    };

    // ldmatrix lane-address components
    const int nRowSel = (lane >> 4) * 8 + (lane & 7);       // non-trans: row within 16
    const int nColSel = ((lane >> 3) & 1) * 8;              // non-trans: k sub-offset
    const int tRowSel = (lane & 7) + ((lane >> 3) & 1) * 8; // trans: k row within 16
    const int tColSel = (lane >> 4) * 8;                    // trans: n sub-offset

    stage(0);
    stage(1);
    for (int t = 0; t < T; t++) {
        if (t + 2 < T) {
            asm volatile("cp.async.wait_group 1;" ::: "memory");
        } else {
            asm volatile("cp.async.wait_group 0;" ::: "memory");
        }
        __syncthreads();                    // tile t published; iter t-1 readers done
        if (t + 2 < T) stage(t + 2);        // overwrites buffer (t-1)%3 — safe

        const uint32_t uKs = uK + (uint32_t)(t % STG) * KV_H * 2;
        const uint32_t uVs = uV + (uint32_t)(t % STG) * KV_H * 2;

        // ---- S = (Q/8) @ K^T : 16 x 64 per warp ----
        float sacc[8][4];
#pragma unroll
        for (int nj = 0; nj < 8; nj++)
#pragma unroll
            for (int r = 0; r < 4; r++) sacc[nj][r] = 0.0f;
#pragma unroll
        for (int ks = 0; ks < 4; ks++) {
            const int kc = ks * 16;
#pragma unroll
            for (int p = 0; p < 4; p++) {
                uint32_t tmp[4];
                ldsm4(tmp, uKs + (uint32_t)((p * 16 + nRowSel) * PW + kc + nColSel) * 2);
                mma16(sacc[2 * p], qf[ks], tmp);
                mma16(sacc[2 * p + 1], qf[ks], tmp + 2);
            }
        }

        // ---- online softmax (P packed to registers) ----
        float mx0 = -1e30f, mx1 = -1e30f;
#pragma unroll
        for (int nj = 0; nj < 8; nj++) {
            mx0 = fmaxf(mx0, fmaxf(sacc[nj][0], sacc[nj][1]));
            mx1 = fmaxf(mx1, fmaxf(sacc[nj][2], sacc[nj][3]));
        }
        mx0 = fmaxf(mx0, __shfl_xor_sync(0xffffffffu, mx0, 1));
        mx0 = fmaxf(mx0, __shfl_xor_sync(0xffffffffu, mx0, 2));
        mx1 = fmaxf(mx1, __shfl_xor_sync(0xffffffffu, mx1, 1));
        mx1 = fmaxf(mx1, __shfl_xor_sync(0xffffffffu, mx1, 2));

        const float mn0 = fmaxf(mrow0, mx0);
        const float mn1 = fmaxf(mrow1, mx1);
        const float sc0 = __expf(mrow0 - mn0);
        const float sc1 = __expf(mrow1 - mn1);
        mrow0 = mn0; mrow1 = mn1;

        uint32_t puint[16];
        float ls0 = 0.0f, ls1 = 0.0f;
#pragma unroll
        for (int nj = 0; nj < 8; nj++) {
            float e0 = __expf(sacc[nj][0] - mn0);
            float e1 = __expf(sacc[nj][1] - mn0);
            float e2 = __expf(sacc[nj][2] - mn1);
            float e3 = __expf(sacc[nj][3] - mn1);
            ls0 += e0 + e1;
            ls1 += e2 + e3;
            puint[2 * nj]     = packh2(e0, e1);
            puint[2 * nj + 1] = packh2(e2, e3);
        }
        ls0 += __shfl_xor_sync(0xffffffffu, ls0, 1);
        ls0 += __shfl_xor_sync(0xffffffffu, ls0, 2);
        ls1 += __shfl_xor_sync(0xffffffffu, ls1, 1);
        ls1 += __shfl_xor_sync(0xffffffffu, ls1, 2);
        lrow0 = lrow0 * sc0 + ls0;
        lrow1 = lrow1 * sc1 + ls1;

#pragma unroll
        for (int nj = 0; nj < 8; nj++) {
            oacc[nj][0] *= sc0; oacc[nj][1] *= sc0;
            oacc[nj][2] *= sc1; oacc[nj][3] *= sc1;
        }

        // ---- O += P @ V  (P from registers; V [keys][dk] via trans) ----
#pragma unroll
        for (int ks = 0; ks < 4; ks++) {
            const int kc = ks * 16;
            uint32_t pf[4] = {puint[4 * ks], puint[4 * ks + 1],
                              puint[4 * ks + 2], puint[4 * ks + 3]};
#pragma unroll
            for (int p = 0; p < 4; p++) {
                uint32_t tmp[4];
                ldsm4t(tmp, uVs + (uint32_t)((kc + tRowSel) * PW + p * 16 + tColSel) * 2);
                mma16(oacc[2 * p], pf, tmp);
                mma16(oacc[2 * p + 1], pf, tmp + 2);
            }
        }
    }

    // ---- epilogue: normalize, write half into concat layout ----
    const float inv0 = 1.0f / lrow0;
    const float inv1 = 1.0f / lrow1;
    const long long row0 = (long long)zb * S_ + m0 + wr + gid;
    const long long row1 = row0 + 8;
    __half* o0 = Och + row0 * D_ + zh * DK_;
    __half* o1 = Och + row1 * D_ + zh * DK_;
#pragma unroll
    for (int nj = 0; nj < 8; nj++) {
        const int c = nj * 8 + tig * 2;
        *reinterpret_cast<__half2*>(o0 + c) =
            __floats2half2_rn(oacc[nj][0] * inv0, oacc[nj][1] * inv0);
        *reinterpret_cast<__half2*>(o1 + c) =
            __floats2half2_rn(oacc[nj][2] * inv1, oacc[nj][3] * inv1);
    }
}

// =====================================================================
// Segmented fp32 -> fp16 conversion (one launch for x + all weights).
// =====================================================================
struct CvtSeg { const float* src; __half* dst; int nblk; };
struct CvtArgs { CvtSeg s[7]; };

__global__ void __launch_bounds__(256)
f2h_all(CvtArgs a)
{
    int b = blockIdx.x;
#pragma unroll
    for (int i = 0; i < 7; i++) {
        if (b < a.s[i].nblk) {
            const float4* src = reinterpret_cast<const float4*>(a.s[i].src);
            uint2* dst = reinterpret_cast<uint2*>(a.s[i].dst);
            int e = b * 256 + threadIdx.x;
            float4 v = src[e];
            __half2 lo = __floats2half2_rn(v.x, v.y);
            __half2 hi = __floats2half2_rn(v.z, v.w);
            uint2 o;
            o.x = *reinterpret_cast<uint32_t*>(&lo);
            o.y = *reinterpret_cast<uint32_t*>(&hi);
            dst[e] = o;
            return;
        }
        b -= a.s[i].nblk;
    }
}

// =====================================================================
// Row LayerNorm, HALF input, 2 rows per 256-thread block.
// =====================================================================
__global__ void __launch_bounds__(256)
layernorm_h2(const __half* __restrict__ in, const float* __restrict__ g,
             const float* __restrict__ b, float* __restrict__ outf,
             __half* __restrict__ outh)
{
    const int tid  = threadIdx.x;
    const int rsel = tid >> 7;                 // 0 or 1: which row
    const int rtid = tid & 127;                // thread within row
    const long long row = (long long)blockIdx.x * 2 + rsel;

    const uint2 hv = reinterpret_cast<const uint2*>(in + row * D_)[rtid];
    __half2 h01 = *reinterpret_cast<const __half2*>(&hv.x);
    __half2 h23 = *reinterpret_cast<const __half2*>(&hv.y);
    float4 v;
    v.x = __low2float(h01); v.y = __high2float(h01);
    v.z = __low2float(h23); v.w = __high2float(h23);

    float s  = v.x + v.y + v.z + v.w;
    float sq = v.x * v.x + v.y * v.y + v.z * v.z + v.w * v.w;
#pragma unroll
    for (int o = 16; o; o >>= 1) {
        s  += __shfl_xor_sync(0xffffffffu, s, o);
        sq += __shfl_xor_sync(0xffffffffu, sq, o);
    }
    __shared__ float ssum[8], ssq[8];          // 8 warps total (4 per row)
    if ((tid & 31) == 0) { ssum[tid >> 5] = s; ssq[tid >> 5] = sq; }
    __syncthreads();
    const int wb = rsel * 4;
    s  = ssum[wb] + ssum[wb + 1] + ssum[wb + 2] + ssum[wb + 3];
    sq = ssq[wb] + ssq[wb + 1] + ssq[wb + 2] + ssq[wb + 3];

    const float mu  = s * (1.0f / D_);
    float var = sq * (1.0f / D_) - mu * mu;
    var = fmaxf(var, 0.0f);
    const float rstd = rsqrtf(var + 1e-5f);

    float4 gg = reinterpret_cast<const float4*>(g)[rtid];
    float4 bb = reinterpret_cast<const float4*>(b)[rtid];
    float4 o4;
    o4.x = (v.x - mu) * rstd * gg.x + bb.x;
    o4.y = (v.y - mu) * rstd * gg.y + bb.y;
    o4.z = (v.z - mu) * rstd * gg.z + bb.z;
    o4.w = (v.w - mu) * rstd * gg.w + bb.w;
    if (outf != nullptr)
        reinterpret_cast<float4*>(outf + row * D_)[rtid] = o4;
    if (outh != nullptr) {
        __half2 lo = __floats2half2_rn(o4.x, o4.y);
        __half2 hi = __floats2half2_rn(o4.z, o4.w);
        uint2 o;
        o.x = *reinterpret_cast<uint32_t*>(&lo);
        o.y = *reinterpret_cast<uint32_t*>(&hi);
        reinterpret_cast<uint2*>(outh + row * D_)[rtid] = o;
    }
}

// =====================================================================
// Launcher
// =====================================================================
static constexpr int SMEM_M4N64S2 = 2 * (128 * 72 + 64 * 72) * 2;    // 55296
static constexpr int SMEM_M2N64S3 = 3 * (64 * 72 + 64 * 72) * 2;     // 55296
static constexpr int SMEM_M4N128S3 = 3 * (128 * 72 + 64 * 136) * 2;  // 107520
static constexpr int SMEM_FLASH  = (128 * 72 + 6 * 64 * 72) * 2;     // 73728

extern "C" void kernel_launch(void* const* d_in, const int* in_sizes, int n_in,
                              void* d_out, int out_size)
{
    (void)in_sizes; (void)n_in; (void)out_size;
    const float* x     = (const float*)d_in[0];
    const float* Wq    = (const float*)d_in[1];
    const float* bq    = (const float*)d_in[2];
    const float* Wk    = (const float*)d_in[3];
    const float* bk    = (const float*)d_in[4];
    const float* Wv    = (const float*)d_in[5];
    const float* bv    = (const float*)d_in[6];
    const float* Wo    = (const float*)d_in[7];
    const float* bo    = (const float*)d_in[8];
    const float* ln1_g = (const float*)d_in[9];
    const float* ln1_b = (const float*)d_in[10];
    const float* W1    = (const float*)d_in[11];
    const float* b1    = (const float*)d_in[12];
    const float* W2    = (const float*)d_in[13];
    const float* b2    = (const float*)d_in[14];
    const float* ln2_g = (const float*)d_in[15];
    const float* ln2_b = (const float*)d_in[16];
    float* out = (float*)d_out;

    __half *xh, *q, *k, *v, *och, *h1h, *hh, *ff, *h2h;
    __half *Wqh, *Wkh, *Wvh, *Woh, *W1h, *W2h;
    cudaGetSymbolAddress((void**)&xh,  g_xh);
    cudaGetSymbolAddress((void**)&q,   g_q);
    cudaGetSymbolAddress((void**)&k,   g_k);
    cudaGetSymbolAddress((void**)&v,   g_v);
    cudaGetSymbolAddress((void**)&och, g_och);
    cudaGetSymbolAddress((void**)&h1h, g_h1h);
    cudaGetSymbolAddress((void**)&hh,  g_hh);
    cudaGetSymbolAddress((void**)&ff,  g_ff);
    cudaGetSymbolAddress((void**)&h2h, g_h2h);
    cudaGetSymbolAddress((void**)&Wqh, g_Wqh);
    cudaGetSymbolAddress((void**)&Wkh, g_Wkh);
    cudaGetSymbolAddress((void**)&Wvh, g_Wvh);
    cudaGetSymbolAddress((void**)&Woh, g_Woh);
    cudaGetSymbolAddress((void**)&W1h, g_W1h);
    cudaGetSymbolAddress((void**)&W2h, g_W2h);

    cudaFuncSetAttribute(gemm_h<4, 64, 2, 0, true>,   cudaFuncAttributeMaxDynamicSharedMemorySize, SMEM_M4N64S2);
    cudaFuncSetAttribute(gemm_h<2, 64, 3, 2, false>,  cudaFuncAttributeMaxDynamicSharedMemorySize, SMEM_M2N64S3);
    cudaFuncSetAttribute(gemm_h<4, 128, 3, 1, false>, cudaFuncAttributeMaxDynamicSharedMemorySize, SMEM_M4N128S3);
    cudaFuncSetAttribute(flash_h,                     cudaFuncAttributeMaxDynamicSharedMemorySize, SMEM_FLASH);

    const Off lin0      = {1, 0, 0};
    const Off oA_qkv    = {H_, (long long)S_ * D_, 0};
    const Off oB_qkv    = {H_, 0, (long long)D_ * DK_};
    const Off oBias_qkv = {H_, 0, (long long)DK_};
    const Off oC_qkv    = {1, (long long)S_ * DK_, 0};

    // ---- 0. one-shot fp32->fp16 conversion ----
    CvtArgs ca;
    ca.s[0] = {x,  xh,  (int)((long long)M_ * D_ / 1024)};
    ca.s[1] = {Wq, Wqh, (int)((long long)H_ * D_ * DK_ / 1024)};
    ca.s[2] = {Wk, Wkh, (int)((long long)H_ * D_ * DK_ / 1024)};
    ca.s[3] = {Wv, Wvh, (int)((long long)H_ * D_ * DK_ / 1024)};
    ca.s[4] = {Wo, Woh, (int)((long long)D_ * D_ / 1024)};
    ca.s[5] = {W1, W1h, (int)((long long)D_ * DF_ / 1024)};
    ca.s[6] = {W2, W2h, (int)((long long)DF_ * D_ / 1024)};
    int totBlk = 0;
    for (int i = 0; i < 7; i++) totBlk += ca.s[i].nblk;
    f2h_all<<<totBlk, 256>>>(ca);

    // ---- 1. merged QKV projections (BM=128, BK=64, T=8, 2-stage -> occ 4) ----
    gemm_h<4, 64, 2, 0, true><<<dim3(3, 16, B_ * H_), 128, SMEM_M4N64S2>>>(
        xh, Wqh, Wkh, Wvh, bq, bk, bv, nullptr, q, k, v,
        S_, DK_, D_, DK_, oA_qkv, oB_qkv, oBias_qkv, oC_qkv);

    // ---- 2. fused flash attention -> half concat layout ----
    flash_h<<<dim3(S_ / 128, B_ * H_), 256, SMEM_FLASH>>>(q, k, v, och);

    // ---- 3. h1h = xh + och @ Wo + bo  (half residual, half out) ----
    gemm_h<2, 64, 3, 2, false><<<dim3(8, 64, 1), 128, SMEM_M2N64S3>>>(
        och, Woh, Woh, Woh, bo, bo, bo, xh, h1h, h1h, h1h,
        M_, D_, D_, D_, lin0, lin0, lin0, lin0);

    // ---- 4. hh = LN1(h1h)  (half in, half out only; 2 rows/block) ----
    layernorm_h2<<<M_ / 2, 256>>>(h1h, ln1_g, ln1_b, nullptr, hh);

    // ---- 5. ff = relu(hh @ W1 + b1)  (BM=128, BN=128) ----
    gemm_h<4, 128, 3, 1, false><<<dim3(16, 32, 1), 256, SMEM_M4N128S3>>>(
        hh, W1h, W1h, W1h, b1, b1, b1, nullptr, ff, ff, ff,
        M_, DF_, D_, DF_, lin0, lin0, lin0, lin0);

    // ---- 6. h2h = hh + ff @ W2 + b2  (half residual, half out) ----
    gemm_h<2, 64, 3, 2, false><<<dim3(8, 64, 1), 128, SMEM_M2N64S3>>>(
        ff, W2h, W2h, W2h, b2, b2, b2, hh, h2h, h2h, h2h,
        M_, D_, DF_, D_, lin0, lin0, lin0, lin0);

    // ---- 7. out = LN2(h2h)  (half in, fp32 out; 2 rows/block) ----
    layernorm_h2<<<M_ / 2, 256>>>(h2h, ln2_g, ln2_b, out, nullptr);
}